// round 15
// baseline (speedup 1.0000x reference)
#include <cuda_runtime.h>

#define T_STEPS 128
#define BATCH   64
#define DFEAT   32
#define NSUP    1024
#define MROWS   8192
#define LSTM_BLOCKS 8
#define NBLOCKS (LSTM_BLOCKS + 256)   // 64 M-tiles x 4 blocks, each 2 N-subtiles

#define OUTS_OFF 0
#define RBF_OFF  32768
#define QK_OFF   (32768 + MROWS*NSUP)

#define LOG2E 1.4426950408889634f

typedef unsigned long long u64;

__device__ __forceinline__ float tanh_hw(float z){
    float r;
    asm("tanh.approx.f32 %0, %1;" : "=f"(r) : "f"(z));
    return r;
}
__device__ __forceinline__ float sigm_hw(float z){
    return fmaf(0.5f, tanh_hw(0.5f*z), 0.5f);
}
__device__ __forceinline__ float ex2_hw(float z){
    float r;
    asm("ex2.approx.f32 %0, %1;" : "=f"(r) : "f"(z));
    return r;
}

// ---- packed fp32x2 helpers ----
__device__ __forceinline__ u64 pack2(float lo, float hi){
    u64 r;
    asm("mov.b64 %0, {%1,%2};" : "=l"(r) : "f"(lo), "f"(hi));
    return r;
}
__device__ __forceinline__ void unpack2(u64 v, float& lo, float& hi){
    asm("mov.b64 {%0,%1}, %2;" : "=f"(lo), "=f"(hi) : "l"(v));
}
__device__ __forceinline__ u64 fma2_(u64 a, u64 b, u64 c){
    u64 d;
    asm("fma.rn.f32x2 %0, %1, %2, %3;" : "=l"(d) : "l"(a), "l"(b), "l"(c));
    return d;
}
__device__ __forceinline__ u64 mul2_(u64 a, u64 b){
    u64 d;
    asm("mul.rn.f32x2 %0, %1, %2;" : "=l"(d) : "l"(a), "l"(b));
    return d;
}
__device__ __forceinline__ u64 add2_(u64 a, u64 b){
    u64 d;
    asm("add.rn.f32x2 %0, %1, %2;" : "=l"(d) : "l"(a), "l"(b));
    return d;
}

__global__ __launch_bounds__(256, 2)
void hyb_kernel(const float* __restrict__ x,
                const float* __restrict__ sv,
                const float* __restrict__ Wf, const float* __restrict__ bf,
                const float* __restrict__ Wi, const float* __restrict__ bi,
                const float* __restrict__ Wu, const float* __restrict__ bu,
                const float* __restrict__ Wo, const float* __restrict__ bo,
                const float* __restrict__ pf, const float* __restrict__ pi,
                const float* __restrict__ pu, const float* __restrict__ po,
                const float* __restrict__ qkp,
                float* __restrict__ out)
{
    if (blockIdx.x < LSTM_BLOCKS) {
        // ========= LSTM role: 8 warps per block, one warp per batch element =========
        int warp = threadIdx.x >> 5;
        int lane = threadIdx.x & 31;
        int b    = blockIdx.x * 8 + warp;   // 0..63
        int sl   = lane & 15;
        int g    = sl >> 2;
        int w    = sl & 3;

        const float* W  = (g==0)?Wf:(g==1)?Wi:(g==2)?Wu:Wo;
        const float* bb = (g==0)?bf:(g==1)?bi:(g==2)?bu:bo;
        const float* pp = (g==0)?pf:(g==1)?pi:(g==2)?pu:po;

        float wx[32];
        #pragma unroll
        for (int d=0; d<32; d++) wx[d] = W[w*36 + d];
        float wh0 = W[w*36+32], wh1 = W[w*36+33], wh2 = W[w*36+34], wh3 = W[w*36+35];
        float bias = bb[w] + pp[w];

        float h0=0.f,h1=0.f,h2=0.f,h3=0.f,cst=0.f;
        const unsigned FULL = 0xffffffffu;

        float dcur;
        {
            const float4* xp = (const float4*)(x + (size_t)b*DFEAT);
            float s0=bias, s1=0.f, s2=0.f, s3=0.f;
            #pragma unroll
            for (int q=0;q<8;q++){
                float4 v = xp[q];
                s0 = fmaf(wx[4*q+0], v.x, s0);
                s1 = fmaf(wx[4*q+1], v.y, s1);
                s2 = fmaf(wx[4*q+2], v.z, s2);
                s3 = fmaf(wx[4*q+3], v.w, s3);
            }
            dcur = (s0+s1)+(s2+s3);
        }

        for (int t=0; t<T_STEPS; t++){
            float theta = dcur;
            theta = fmaf(wh0,h0,theta);
            theta = fmaf(wh1,h1,theta);
            theta = fmaf(wh2,h2,theta);
            theta = fmaf(wh3,h3,theta);
            float cth = __cosf(theta);

            float dnext = bias;
            if (t < T_STEPS-1){
                const float4* xp = (const float4*)(x + ((size_t)(t+1)*BATCH + b)*DFEAT);
                float s0=bias, s1=0.f, s2=0.f, s3=0.f;
                #pragma unroll
                for (int q=0;q<8;q++){
                    float4 v = __ldg(&xp[q]);
                    s0 = fmaf(wx[4*q+0], v.x, s0);
                    s1 = fmaf(wx[4*q+1], v.y, s1);
                    s2 = fmaf(wx[4*q+2], v.z, s2);
                    s3 = fmaf(wx[4*q+3], v.w, s3);
                }
                dnext = (s0+s1)+(s2+s3);
            }

            int base = lane & ~3;
            float c0 = __shfl_sync(FULL, cth, base+0);
            float c1 = __shfl_sync(FULL, cth, base+1);
            float c2 = __shfl_sync(FULL, cth, base+2);
            float c3 = __shfl_sync(FULL, cth, base+3);
            float p01  = c0*c1;
            float p012 = p01*c2;
            float z = (w==0) ? c1*c2*c3 : (w==1) ? p01 : (w==2) ? p012 : p012*c3;
            float val = (g==2) ? tanh_hw(z) : sigm_hw(z);

            int hb = lane & 16;
            float fv = __shfl_sync(FULL, val, hb + 0  + w);
            float iv = __shfl_sync(FULL, val, hb + 4  + w);
            float uv = __shfl_sync(FULL, val, hb + 8  + w);
            float ov = __shfl_sync(FULL, val, hb + 12 + w);

            cst = fmaf(fv, cst, iv*uv);
            float ht = ov * tanh_hw(cst);
            if (lane < 4) out[OUTS_OFF + t*(BATCH*4) + b*4 + w] = ht;

            h0 = __shfl_sync(FULL, ht, base+0);
            h1 = __shfl_sync(FULL, ht, base+1);
            h2 = __shfl_sync(FULL, ht, base+2);
            h3 = __shfl_sync(FULL, ht, base+3);
            dcur = dnext;
        }
        return;
    }

    // ===== rbf + qk role: 2 N-adjacent 128x128 tiles, single prologue, 1 barrier =====
    __shared__ __align__(16) float xs[32][132];      // k-major x tile
    __shared__ __align__(16) float ss[2][32][132];   // k-major s tiles (both subtiles)
    __shared__ float xrow[128][9];                   // cos u[4], sin u[4], ||x||^2 * log2e
    __shared__ float srow[2][128][9];                // cos v[4], -sin v[4], ||s||^2 * log2e

    int bid2 = blockIdx.x - LSTM_BLOCKS;
    int mt = bid2 >> 2;
    int np = bid2 & 3;
    int m0 = mt * 128;
    int n0base = np * 256;
    int tid = threadIdx.x;
    int rbase = tid >> 3;
    int kc    = (tid & 7) * 4;

    // ---- single prologue: all gmem traffic up front ----
    {
        #pragma unroll
        for (int pass=0; pass<4; pass++){
            int r = rbase + pass*32;
            float4 v  = *(const float4*)(x  + (size_t)(m0 + r)*DFEAT + kc);
            float4 u0 = *(const float4*)(sv + (size_t)(n0base + r)*DFEAT + kc);
            float4 u1 = *(const float4*)(sv + (size_t)(n0base + 128 + r)*DFEAT + kc);
            xs[kc+0][r]=v.x;  xs[kc+1][r]=v.y;  xs[kc+2][r]=v.z;  xs[kc+3][r]=v.w;
            ss[0][kc+0][r]=u0.x; ss[0][kc+1][r]=u0.y; ss[0][kc+2][r]=u0.z; ss[0][kc+3][r]=u0.w;
            ss[1][kc+0][r]=u1.x; ss[1][kc+1][r]=u1.y; ss[1][kc+2][r]=u1.z; ss[1][kc+3][r]=u1.w;
        }
    }
    if (tid < 128){   // xrow factors
        const float4* xp = (const float4*)(x + (size_t)(m0 + tid)*DFEAT);
        float4 v0 = xp[0];
        float nrm = 0.f;
        #pragma unroll
        for (int q=0;q<8;q++){
            float4 v = xp[q];
            nrm = fmaf(v.x,v.x,nrm); nrm = fmaf(v.y,v.y,nrm);
            nrm = fmaf(v.z,v.z,nrm); nrm = fmaf(v.w,v.w,nrm);
        }
        float fw[4] = {v0.x, v0.y, v0.z, v0.w};
        #pragma unroll
        for (int w=0; w<4; w++){
            float th = fmaf(fw[w], 0.5f, qkp[w]*0.5f);
            float s_, c_;
            __sincosf(th, &s_, &c_);
            xrow[tid][w]   = c_;
            xrow[tid][4+w] = s_;
        }
        xrow[tid][8] = nrm * LOG2E;
    } else {          // srow factors for BOTH subtiles
        int r = tid - 128;
        #pragma unroll
        for (int sub=0; sub<2; sub++){
            const float4* sp = (const float4*)(sv + (size_t)(n0base + sub*128 + r)*DFEAT);
            float4 v0 = sp[0];
            float nrm = 0.f;
            #pragma unroll
            for (int q=0;q<8;q++){
                float4 v = sp[q];
                nrm = fmaf(v.x,v.x,nrm); nrm = fmaf(v.y,v.y,nrm);
                nrm = fmaf(v.z,v.z,nrm); nrm = fmaf(v.w,v.w,nrm);
            }
            float fw[4] = {v0.x, v0.y, v0.z, v0.w};
            #pragma unroll
            for (int w=0; w<4; w++){
                float th = fmaf(fw[w], 0.5f, qkp[w]*0.5f);
                float s_, c_;
                __sincosf(th, &s_, &c_);
                srow[sub][r][w]   = c_;
                srow[sub][r][4+w] = -s_;     // store sin negated
            }
            srow[sub][r][8] = nrm * LOG2E;
        }
    }
    __syncthreads();   // the only barrier

    int tx = tid & 15;
    int ty = tid >> 4;
    float* rbf_out = out + RBF_OFF;
    float* qk_out  = out + QK_OFF;
    const u64 TWOL = pack2(2.0f*LOG2E, 2.0f*LOG2E);

    #pragma unroll 1
    for (int sub = 0; sub < 2; sub++){
        int n0 = n0base + sub*128;
        const float (*ssb)[132] = ss[sub];
        const float (*srb)[9]   = srow[sub];

        // ---- main GEMM loop: 8 rows x 8 cols per thread, packed f32x2 along N ----
        u64 acc2[2][4][2][2];
        #pragma unroll
        for (int ii=0;ii<2;ii++)
            #pragma unroll
            for (int r=0;r<4;r++)
                #pragma unroll
                for (int jj=0;jj<2;jj++){ acc2[ii][r][jj][0]=0ull; acc2[ii][r][jj][1]=0ull; }

        #pragma unroll 8
        for (int k=0; k<32; k++){
            float4 a0 = ((const float4*)xs[k])[ty];
            float4 a1 = ((const float4*)xs[k])[ty+16];
            ulonglong2 B0 = ((const ulonglong2*)ssb[k])[tx];
            ulonglong2 B1 = ((const ulonglong2*)ssb[k])[tx+16];
            u64 aa;
            aa = pack2(a0.x,a0.x);
            acc2[0][0][0][0]=fma2_(aa,B0.x,acc2[0][0][0][0]); acc2[0][0][0][1]=fma2_(aa,B0.y,acc2[0][0][0][1]);
            acc2[0][0][1][0]=fma2_(aa,B1.x,acc2[0][0][1][0]); acc2[0][0][1][1]=fma2_(aa,B1.y,acc2[0][0][1][1]);
            aa = pack2(a0.y,a0.y);
            acc2[0][1][0][0]=fma2_(aa,B0.x,acc2[0][1][0][0]); acc2[0][1][0][1]=fma2_(aa,B0.y,acc2[0][1][0][1]);
            acc2[0][1][1][0]=fma2_(aa,B1.x,acc2[0][1][1][0]); acc2[0][1][1][1]=fma2_(aa,B1.y,acc2[0][1][1][1]);
            aa = pack2(a0.z,a0.z);
            acc2[0][2][0][0]=fma2_(aa,B0.x,acc2[0][2][0][0]); acc2[0][2][0][1]=fma2_(aa,B0.y,acc2[0][2][0][1]);
            acc2[0][2][1][0]=fma2_(aa,B1.x,acc2[0][2][1][0]); acc2[0][2][1][1]=fma2_(aa,B1.y,acc2[0][2][1][1]);
            aa = pack2(a0.w,a0.w);
            acc2[0][3][0][0]=fma2_(aa,B0.x,acc2[0][3][0][0]); acc2[0][3][0][1]=fma2_(aa,B0.y,acc2[0][3][0][1]);
            acc2[0][3][1][0]=fma2_(aa,B1.x,acc2[0][3][1][0]); acc2[0][3][1][1]=fma2_(aa,B1.y,acc2[0][3][1][1]);
            aa = pack2(a1.x,a1.x);
            acc2[1][0][0][0]=fma2_(aa,B0.x,acc2[1][0][0][0]); acc2[1][0][0][1]=fma2_(aa,B0.y,acc2[1][0][0][1]);
            acc2[1][0][1][0]=fma2_(aa,B1.x,acc2[1][0][1][0]); acc2[1][0][1][1]=fma2_(aa,B1.y,acc2[1][0][1][1]);
            aa = pack2(a1.y,a1.y);
            acc2[1][1][0][0]=fma2_(aa,B0.x,acc2[1][1][0][0]); acc2[1][1][0][1]=fma2_(aa,B0.y,acc2[1][1][0][1]);
            acc2[1][1][1][0]=fma2_(aa,B1.x,acc2[1][1][1][0]); acc2[1][1][1][1]=fma2_(aa,B1.y,acc2[1][1][1][1]);
            aa = pack2(a1.z,a1.z);
            acc2[1][2][0][0]=fma2_(aa,B0.x,acc2[1][2][0][0]); acc2[1][2][0][1]=fma2_(aa,B0.y,acc2[1][2][0][1]);
            acc2[1][2][1][0]=fma2_(aa,B1.x,acc2[1][2][1][0]); acc2[1][2][1][1]=fma2_(aa,B1.y,acc2[1][2][1][1]);
            aa = pack2(a1.w,a1.w);
            acc2[1][3][0][0]=fma2_(aa,B0.x,acc2[1][3][0][0]); acc2[1][3][0][1]=fma2_(aa,B0.y,acc2[1][3][0][1]);
            acc2[1][3][1][0]=fma2_(aa,B1.x,acc2[1][3][1][0]); acc2[1][3][1][1]=fma2_(aa,B1.y,acc2[1][3][1][1]);
        }

        const int ncol0 = n0 + tx*4;

        // ---- interleaved epilogue: rbf (MUFU) + qk (FMA) per row-group ----
        u64 nsnA0 = pack2(-srb[tx*4+0][8], -srb[tx*4+1][8]);
        u64 nsnA1 = pack2(-srb[tx*4+2][8], -srb[tx*4+3][8]);
        u64 nsnB0 = pack2(-srb[tx*4+64][8], -srb[tx*4+65][8]);
        u64 nsnB1 = pack2(-srb[tx*4+66][8], -srb[tx*4+67][8]);
        u64 cvA[2][4], nsvA[2][4], cvB[2][4], nsvB[2][4];
        #pragma unroll
        for (int p=0; p<2; p++){
            int c0 = tx*4 + 2*p, c1 = c0 + 1;
            #pragma unroll
            for (int w=0; w<4; w++){
                cvA[p][w]  = pack2(srb[c0][w],    srb[c1][w]);
                nsvA[p][w] = pack2(srb[c0][4+w],  srb[c1][4+w]);     // already negated
                cvB[p][w]  = pack2(srb[c0+64][w], srb[c1+64][w]);
                nsvB[p][w] = pack2(srb[c0+64][4+w], srb[c1+64][4+w]);
            }
        }
        const u64 ABSM = 0x7FFFFFFF7FFFFFFFull;

        #pragma unroll
        for (int ii=0; ii<2; ii++){
            #pragma unroll
            for (int r=0; r<4; r++){
                int mi = ty*4 + r + 64*ii;
                int m = m0 + mi;
                float xn = xrow[mi][8];
                u64 nxn2 = pack2(-xn, -xn);

                // rbf arguments (FMA) -> launch MUFU ex2 early
                u64 g0 = fma2_(acc2[ii][r][0][0], TWOL, add2_(nxn2, nsnA0));
                u64 g1 = fma2_(acc2[ii][r][0][1], TWOL, add2_(nxn2, nsnA1));
                u64 g2 = fma2_(acc2[ii][r][1][0], TWOL, add2_(nxn2, nsnB0));
                u64 g3 = fma2_(acc2[ii][r][1][1], TWOL, add2_(nxn2, nsnB1));
                float4 o0, o1;
                unpack2(g0, o0.x, o0.y);  unpack2(g1, o0.z, o0.w);
                unpack2(g2, o1.x, o1.y);  unpack2(g3, o1.z, o1.w);
                o0.x = ex2_hw(o0.x); o0.y = ex2_hw(o0.y);
                o0.z = ex2_hw(o0.z); o0.w = ex2_hw(o0.w);
                o1.x = ex2_hw(o1.x); o1.y = ex2_hw(o1.y);
                o1.z = ex2_hw(o1.z); o1.w = ex2_hw(o1.w);

                // qk products (FMA pipe) overlap the MUFU latency above
                u64 cu2[4], su2[4];
                #pragma unroll
                for (int w=0; w<4; w++){
                    float cu = xrow[mi][w], su = xrow[mi][4+w];
                    cu2[w] = pack2(cu,cu); su2[w] = pack2(su,su);
                }
                ulonglong2 st0, st1;
                #pragma unroll
                for (int p=0; p<2; p++){
                    u64 t0 = fma2_(cu2[0], cvA[p][0], mul2_(su2[0], nsvA[p][0]));
                    u64 t1 = fma2_(cu2[1], cvA[p][1], mul2_(su2[1], nsvA[p][1]));
                    u64 t2 = fma2_(cu2[2], cvA[p][2], mul2_(su2[2], nsvA[p][2]));
                    u64 t3 = fma2_(cu2[3], cvA[p][3], mul2_(su2[3], nsvA[p][3]));
                    u64 q = mul2_(mul2_(t0,t1), mul2_(t2,t3)) & ABSM;
                    if (p==0) st0.x = q; else st0.y = q;
                    u64 v0 = fma2_(cu2[0], cvB[p][0], mul2_(su2[0], nsvB[p][0]));
                    u64 v1 = fma2_(cu2[1], cvB[p][1], mul2_(su2[1], nsvB[p][1]));
                    u64 v2 = fma2_(cu2[2], cvB[p][2], mul2_(su2[2], nsvB[p][2]));
                    u64 v3 = fma2_(cu2[3], cvB[p][3], mul2_(su2[3], nsvB[p][3]));
                    u64 qq = mul2_(mul2_(v0,v1), mul2_(v2,v3)) & ABSM;
                    if (p==0) st1.x = qq; else st1.y = qq;
                }

                *(float4*)(rbf_out + (size_t)m*NSUP + ncol0)      = o0;
                *(float4*)(rbf_out + (size_t)m*NSUP + ncol0 + 64) = o1;
                *(ulonglong2*)(qk_out + (size_t)m*NSUP + ncol0)      = st0;
                *(ulonglong2*)(qk_out + (size_t)m*NSUP + ncol0 + 64) = st1;
            }
        }
    }
}

extern "C" void kernel_launch(void* const* d_in, const int* in_sizes, int n_in,
                              void* d_out, int out_size)
{
    const float* x   = (const float*)d_in[0];
    const float* sv  = (const float*)d_in[1];
    const float* Wf  = (const float*)d_in[2];
    const float* bf  = (const float*)d_in[3];
    const float* Wi  = (const float*)d_in[4];
    const float* bi  = (const float*)d_in[5];
    const float* Wu  = (const float*)d_in[6];
    const float* bu  = (const float*)d_in[7];
    const float* Wo  = (const float*)d_in[8];
    const float* bo  = (const float*)d_in[9];
    const float* pf  = (const float*)d_in[10];
    const float* pi_ = (const float*)d_in[11];
    const float* pu  = (const float*)d_in[12];
    const float* po  = (const float*)d_in[13];
    const float* qkp = (const float*)d_in[14];

    hyb_kernel<<<NBLOCKS, 256>>>(x, sv, Wf, bf, Wi, bi, Wu, bu, Wo, bo,
                                 pf, pi_, pu, po, qkp, (float*)d_out);
}

// round 16
// speedup vs baseline: 1.3425x; 1.3425x over previous
#include <cuda_runtime.h>

#define T_STEPS 128
#define BATCH   64
#define DFEAT   32
#define NSUP    1024
#define MROWS   8192
#define LSTM_BLOCKS 8
#define NBLOCKS (LSTM_BLOCKS + 256)   // 64 M-tiles x 4 blocks, each 2 N-subtiles

#define OUTS_OFF 0
#define RBF_OFF  32768
#define QK_OFF   (32768 + MROWS*NSUP)

#define LOG2E 1.4426950408889634f

typedef unsigned long long u64;

__device__ __forceinline__ float tanh_hw(float z){
    float r;
    asm("tanh.approx.f32 %0, %1;" : "=f"(r) : "f"(z));
    return r;
}
__device__ __forceinline__ float sigm_hw(float z){
    return fmaf(0.5f, tanh_hw(0.5f*z), 0.5f);
}
__device__ __forceinline__ float ex2_hw(float z){
    float r;
    asm("ex2.approx.f32 %0, %1;" : "=f"(r) : "f"(z));
    return r;
}

// ---- packed fp32x2 helpers ----
__device__ __forceinline__ u64 pack2(float lo, float hi){
    u64 r;
    asm("mov.b64 %0, {%1,%2};" : "=l"(r) : "f"(lo), "f"(hi));
    return r;
}
__device__ __forceinline__ void unpack2(u64 v, float& lo, float& hi){
    asm("mov.b64 {%0,%1}, %2;" : "=f"(lo), "=f"(hi) : "l"(v));
}
__device__ __forceinline__ u64 fma2_(u64 a, u64 b, u64 c){
    u64 d;
    asm("fma.rn.f32x2 %0, %1, %2, %3;" : "=l"(d) : "l"(a), "l"(b), "l"(c));
    return d;
}
__device__ __forceinline__ u64 mul2_(u64 a, u64 b){
    u64 d;
    asm("mul.rn.f32x2 %0, %1, %2;" : "=l"(d) : "l"(a), "l"(b));
    return d;
}
__device__ __forceinline__ u64 add2_(u64 a, u64 b){
    u64 d;
    asm("add.rn.f32x2 %0, %1, %2;" : "=l"(d) : "l"(a), "l"(b));
    return d;
}

__global__ __launch_bounds__(256, 2)
void hyb_kernel(const float* __restrict__ x,
                const float* __restrict__ sv,
                const float* __restrict__ Wf, const float* __restrict__ bf,
                const float* __restrict__ Wi, const float* __restrict__ bi,
                const float* __restrict__ Wu, const float* __restrict__ bu,
                const float* __restrict__ Wo, const float* __restrict__ bo,
                const float* __restrict__ pf, const float* __restrict__ pi,
                const float* __restrict__ pu, const float* __restrict__ po,
                const float* __restrict__ qkp,
                float* __restrict__ out)
{
    if (blockIdx.x < LSTM_BLOCKS) {
        // ========= LSTM role: 8 warps per block, one warp per batch element =========
        int warp = threadIdx.x >> 5;
        int lane = threadIdx.x & 31;
        int b    = blockIdx.x * 8 + warp;   // 0..63
        int sl   = lane & 15;
        int g    = sl >> 2;
        int w    = sl & 3;

        const float* W  = (g==0)?Wf:(g==1)?Wi:(g==2)?Wu:Wo;
        const float* bb = (g==0)?bf:(g==1)?bi:(g==2)?bu:bo;
        const float* pp = (g==0)?pf:(g==1)?pi:(g==2)?pu:po;

        float wx[32];
        #pragma unroll
        for (int d=0; d<32; d++) wx[d] = W[w*36 + d];
        float wh0 = W[w*36+32], wh1 = W[w*36+33], wh2 = W[w*36+34], wh3 = W[w*36+35];
        float bias = bb[w] + pp[w];

        float h0=0.f,h1=0.f,h2=0.f,h3=0.f,cst=0.f;
        const unsigned FULL = 0xffffffffu;

        float dcur;
        {
            const float4* xp = (const float4*)(x + (size_t)b*DFEAT);
            float s0=bias, s1=0.f, s2=0.f, s3=0.f;
            #pragma unroll
            for (int q=0;q<8;q++){
                float4 v = xp[q];
                s0 = fmaf(wx[4*q+0], v.x, s0);
                s1 = fmaf(wx[4*q+1], v.y, s1);
                s2 = fmaf(wx[4*q+2], v.z, s2);
                s3 = fmaf(wx[4*q+3], v.w, s3);
            }
            dcur = (s0+s1)+(s2+s3);
        }

        for (int t=0; t<T_STEPS; t++){
            float theta = dcur;
            theta = fmaf(wh0,h0,theta);
            theta = fmaf(wh1,h1,theta);
            theta = fmaf(wh2,h2,theta);
            theta = fmaf(wh3,h3,theta);
            float cth = __cosf(theta);

            float dnext = bias;
            if (t < T_STEPS-1){
                const float4* xp = (const float4*)(x + ((size_t)(t+1)*BATCH + b)*DFEAT);
                float s0=bias, s1=0.f, s2=0.f, s3=0.f;
                #pragma unroll
                for (int q=0;q<8;q++){
                    float4 v = __ldg(&xp[q]);
                    s0 = fmaf(wx[4*q+0], v.x, s0);
                    s1 = fmaf(wx[4*q+1], v.y, s1);
                    s2 = fmaf(wx[4*q+2], v.z, s2);
                    s3 = fmaf(wx[4*q+3], v.w, s3);
                }
                dnext = (s0+s1)+(s2+s3);
            }

            int base = lane & ~3;
            float c0 = __shfl_sync(FULL, cth, base+0);
            float c1 = __shfl_sync(FULL, cth, base+1);
            float c2 = __shfl_sync(FULL, cth, base+2);
            float c3 = __shfl_sync(FULL, cth, base+3);
            float p01  = c0*c1;
            float p012 = p01*c2;
            float z = (w==0) ? c1*c2*c3 : (w==1) ? p01 : (w==2) ? p012 : p012*c3;
            float val = (g==2) ? tanh_hw(z) : sigm_hw(z);

            int hb = lane & 16;
            float fv = __shfl_sync(FULL, val, hb + 0  + w);
            float iv = __shfl_sync(FULL, val, hb + 4  + w);
            float uv = __shfl_sync(FULL, val, hb + 8  + w);
            float ov = __shfl_sync(FULL, val, hb + 12 + w);

            cst = fmaf(fv, cst, iv*uv);
            float ht = ov * tanh_hw(cst);
            if (lane < 4) out[OUTS_OFF + t*(BATCH*4) + b*4 + w] = ht;

            h0 = __shfl_sync(FULL, ht, base+0);
            h1 = __shfl_sync(FULL, ht, base+1);
            h2 = __shfl_sync(FULL, ht, base+2);
            h3 = __shfl_sync(FULL, ht, base+3);
            dcur = dnext;
        }
        return;
    }

    // ===== rbf + qk role: 2 N-adjacent 128x128 tiles, single prologue, 1 barrier =====
    __shared__ __align__(16) float xs[32][132];      // k-major x tile
    __shared__ __align__(16) float ss[2][32][132];   // k-major s tiles (both subtiles)
    __shared__ float xrow[128][9];                   // cos u[4], sin u[4], ||x||^2 * log2e
    __shared__ float srow[2][128][9];                // cos v[4], -sin v[4], ||s||^2 * log2e

    int bid2 = blockIdx.x - LSTM_BLOCKS;
    int mt = bid2 >> 2;
    int np = bid2 & 3;
    int m0 = mt * 128;
    int n0base = np * 256;
    int tid = threadIdx.x;
    int rbase = tid >> 3;
    int kc    = (tid & 7) * 4;

    // ---- single prologue: all gmem traffic up front ----
    {
        #pragma unroll
        for (int pass=0; pass<4; pass++){
            int r = rbase + pass*32;
            float4 v  = *(const float4*)(x  + (size_t)(m0 + r)*DFEAT + kc);
            float4 u0 = *(const float4*)(sv + (size_t)(n0base + r)*DFEAT + kc);
            float4 u1 = *(const float4*)(sv + (size_t)(n0base + 128 + r)*DFEAT + kc);
            xs[kc+0][r]=v.x;  xs[kc+1][r]=v.y;  xs[kc+2][r]=v.z;  xs[kc+3][r]=v.w;
            ss[0][kc+0][r]=u0.x; ss[0][kc+1][r]=u0.y; ss[0][kc+2][r]=u0.z; ss[0][kc+3][r]=u0.w;
            ss[1][kc+0][r]=u1.x; ss[1][kc+1][r]=u1.y; ss[1][kc+2][r]=u1.z; ss[1][kc+3][r]=u1.w;
        }
    }
    if (tid < 128){   // xrow factors
        const float4* xp = (const float4*)(x + (size_t)(m0 + tid)*DFEAT);
        float4 v0 = xp[0];
        float nrm = 0.f;
        #pragma unroll
        for (int q=0;q<8;q++){
            float4 v = xp[q];
            nrm = fmaf(v.x,v.x,nrm); nrm = fmaf(v.y,v.y,nrm);
            nrm = fmaf(v.z,v.z,nrm); nrm = fmaf(v.w,v.w,nrm);
        }
        float fw[4] = {v0.x, v0.y, v0.z, v0.w};
        #pragma unroll
        for (int w=0; w<4; w++){
            float th = fmaf(fw[w], 0.5f, qkp[w]*0.5f);
            float s_, c_;
            __sincosf(th, &s_, &c_);
            xrow[tid][w]   = c_;
            xrow[tid][4+w] = s_;
        }
        xrow[tid][8] = nrm * LOG2E;
    } else {          // srow factors for BOTH subtiles
        int r = tid - 128;
        #pragma unroll
        for (int sub=0; sub<2; sub++){
            const float4* sp = (const float4*)(sv + (size_t)(n0base + sub*128 + r)*DFEAT);
            float4 v0 = sp[0];
            float nrm = 0.f;
            #pragma unroll
            for (int q=0;q<8;q++){
                float4 v = sp[q];
                nrm = fmaf(v.x,v.x,nrm); nrm = fmaf(v.y,v.y,nrm);
                nrm = fmaf(v.z,v.z,nrm); nrm = fmaf(v.w,v.w,nrm);
            }
            float fw[4] = {v0.x, v0.y, v0.z, v0.w};
            #pragma unroll
            for (int w=0; w<4; w++){
                float th = fmaf(fw[w], 0.5f, qkp[w]*0.5f);
                float s_, c_;
                __sincosf(th, &s_, &c_);
                srow[sub][r][w]   = c_;
                srow[sub][r][4+w] = -s_;     // store sin negated
            }
            srow[sub][r][8] = nrm * LOG2E;
        }
    }
    __syncthreads();   // the only barrier

    int tx = tid & 15;
    int ty = tid >> 4;
    float* rbf_out = out + RBF_OFF;
    float* qk_out  = out + QK_OFF;
    const u64 TWOL = pack2(2.0f*LOG2E, 2.0f*LOG2E);

    #pragma unroll 1
    for (int sub = 0; sub < 2; sub++){
        int n0 = n0base + sub*128;
        const float (*ssb)[132] = ss[sub];
        const float (*srb)[9]   = srow[sub];

        // ---- main GEMM loop: 8 rows x 8 cols per thread, packed f32x2 along N ----
        u64 acc2[2][4][2][2];
        #pragma unroll
        for (int ii=0;ii<2;ii++)
            #pragma unroll
            for (int r=0;r<4;r++)
                #pragma unroll
                for (int jj=0;jj<2;jj++){ acc2[ii][r][jj][0]=0ull; acc2[ii][r][jj][1]=0ull; }

        #pragma unroll 8
        for (int k=0; k<32; k++){
            float4 a0 = ((const float4*)xs[k])[ty];
            float4 a1 = ((const float4*)xs[k])[ty+16];
            ulonglong2 B0 = ((const ulonglong2*)ssb[k])[tx];
            ulonglong2 B1 = ((const ulonglong2*)ssb[k])[tx+16];
            u64 aa;
            aa = pack2(a0.x,a0.x);
            acc2[0][0][0][0]=fma2_(aa,B0.x,acc2[0][0][0][0]); acc2[0][0][0][1]=fma2_(aa,B0.y,acc2[0][0][0][1]);
            acc2[0][0][1][0]=fma2_(aa,B1.x,acc2[0][0][1][0]); acc2[0][0][1][1]=fma2_(aa,B1.y,acc2[0][0][1][1]);
            aa = pack2(a0.y,a0.y);
            acc2[0][1][0][0]=fma2_(aa,B0.x,acc2[0][1][0][0]); acc2[0][1][0][1]=fma2_(aa,B0.y,acc2[0][1][0][1]);
            acc2[0][1][1][0]=fma2_(aa,B1.x,acc2[0][1][1][0]); acc2[0][1][1][1]=fma2_(aa,B1.y,acc2[0][1][1][1]);
            aa = pack2(a0.z,a0.z);
            acc2[0][2][0][0]=fma2_(aa,B0.x,acc2[0][2][0][0]); acc2[0][2][0][1]=fma2_(aa,B0.y,acc2[0][2][0][1]);
            acc2[0][2][1][0]=fma2_(aa,B1.x,acc2[0][2][1][0]); acc2[0][2][1][1]=fma2_(aa,B1.y,acc2[0][2][1][1]);
            aa = pack2(a0.w,a0.w);
            acc2[0][3][0][0]=fma2_(aa,B0.x,acc2[0][3][0][0]); acc2[0][3][0][1]=fma2_(aa,B0.y,acc2[0][3][0][1]);
            acc2[0][3][1][0]=fma2_(aa,B1.x,acc2[0][3][1][0]); acc2[0][3][1][1]=fma2_(aa,B1.y,acc2[0][3][1][1]);
            aa = pack2(a1.x,a1.x);
            acc2[1][0][0][0]=fma2_(aa,B0.x,acc2[1][0][0][0]); acc2[1][0][0][1]=fma2_(aa,B0.y,acc2[1][0][0][1]);
            acc2[1][0][1][0]=fma2_(aa,B1.x,acc2[1][0][1][0]); acc2[1][0][1][1]=fma2_(aa,B1.y,acc2[1][0][1][1]);
            aa = pack2(a1.y,a1.y);
            acc2[1][1][0][0]=fma2_(aa,B0.x,acc2[1][1][0][0]); acc2[1][1][0][1]=fma2_(aa,B0.y,acc2[1][1][0][1]);
            acc2[1][1][1][0]=fma2_(aa,B1.x,acc2[1][1][1][0]); acc2[1][1][1][1]=fma2_(aa,B1.y,acc2[1][1][1][1]);
            aa = pack2(a1.z,a1.z);
            acc2[1][2][0][0]=fma2_(aa,B0.x,acc2[1][2][0][0]); acc2[1][2][0][1]=fma2_(aa,B0.y,acc2[1][2][0][1]);
            acc2[1][2][1][0]=fma2_(aa,B1.x,acc2[1][2][1][0]); acc2[1][2][1][1]=fma2_(aa,B1.y,acc2[1][2][1][1]);
            aa = pack2(a1.w,a1.w);
            acc2[1][3][0][0]=fma2_(aa,B0.x,acc2[1][3][0][0]); acc2[1][3][0][1]=fma2_(aa,B0.y,acc2[1][3][0][1]);
            acc2[1][3][1][0]=fma2_(aa,B1.x,acc2[1][3][1][0]); acc2[1][3][1][1]=fma2_(aa,B1.y,acc2[1][3][1][1]);
        }

        const int ncol0 = n0 + tx*4;

        // ---- rbf epilogue: 2^(2L*dot - L*xn - L*sn) via MUFU ex2 ----
        {
            u64 nsnA0 = pack2(-srb[tx*4+0][8], -srb[tx*4+1][8]);
            u64 nsnA1 = pack2(-srb[tx*4+2][8], -srb[tx*4+3][8]);
            u64 nsnB0 = pack2(-srb[tx*4+64][8], -srb[tx*4+65][8]);
            u64 nsnB1 = pack2(-srb[tx*4+66][8], -srb[tx*4+67][8]);
            #pragma unroll
            for (int ii=0; ii<2; ii++){
                #pragma unroll
                for (int r=0; r<4; r++){
                    int mi = ty*4 + r + 64*ii;
                    float xn = xrow[mi][8];
                    u64 nxn2 = pack2(-xn, -xn);
                    int m = m0 + mi;
                    u64 g0 = fma2_(acc2[ii][r][0][0], TWOL, add2_(nxn2, nsnA0));
                    u64 g1 = fma2_(acc2[ii][r][0][1], TWOL, add2_(nxn2, nsnA1));
                    u64 g2 = fma2_(acc2[ii][r][1][0], TWOL, add2_(nxn2, nsnB0));
                    u64 g3 = fma2_(acc2[ii][r][1][1], TWOL, add2_(nxn2, nsnB1));
                    float4 o0, o1;
                    unpack2(g0, o0.x, o0.y);  unpack2(g1, o0.z, o0.w);
                    unpack2(g2, o1.x, o1.y);  unpack2(g3, o1.z, o1.w);
                    o0.x = ex2_hw(o0.x); o0.y = ex2_hw(o0.y);
                    o0.z = ex2_hw(o0.z); o0.w = ex2_hw(o0.w);
                    o1.x = ex2_hw(o1.x); o1.y = ex2_hw(o1.y);
                    o1.z = ex2_hw(o1.z); o1.w = ex2_hw(o1.w);
                    *(float4*)(rbf_out + (size_t)m*NSUP + ncol0)      = o0;
                    *(float4*)(rbf_out + (size_t)m*NSUP + ncol0 + 64) = o1;
                }
            }
        }

        // ---- qk epilogue: |prod_w (cu*cv - su*sv)| ----
        {
            u64 cvA[2][4], nsvA[2][4], cvB[2][4], nsvB[2][4];
            #pragma unroll
            for (int p=0; p<2; p++){
                int c0 = tx*4 + 2*p, c1 = c0 + 1;
                #pragma unroll
                for (int w=0; w<4; w++){
                    cvA[p][w]  = pack2(srb[c0][w],    srb[c1][w]);
                    nsvA[p][w] = pack2(srb[c0][4+w],  srb[c1][4+w]);    // already negated
                    cvB[p][w]  = pack2(srb[c0+64][w], srb[c1+64][w]);
                    nsvB[p][w] = pack2(srb[c0+64][4+w], srb[c1+64][4+w]);
                }
            }
            const u64 ABSM = 0x7FFFFFFF7FFFFFFFull;
            #pragma unroll
            for (int ii=0; ii<2; ii++){
                #pragma unroll
                for (int r=0; r<4; r++){
                    int mi = ty*4 + r + 64*ii;
                    int m = m0 + mi;
                    u64 cu2[4], su2[4];
                    #pragma unroll
                    for (int w=0; w<4; w++){
                        float cu = xrow[mi][w], su = xrow[mi][4+w];
                        cu2[w] = pack2(cu,cu); su2[w] = pack2(su,su);
                    }
                    ulonglong2 st0, st1;
                    #pragma unroll
                    for (int p=0; p<2; p++){
                        u64 t0 = fma2_(cu2[0], cvA[p][0], mul2_(su2[0], nsvA[p][0]));
                        u64 t1 = fma2_(cu2[1], cvA[p][1], mul2_(su2[1], nsvA[p][1]));
                        u64 t2 = fma2_(cu2[2], cvA[p][2], mul2_(su2[2], nsvA[p][2]));
                        u64 t3 = fma2_(cu2[3], cvA[p][3], mul2_(su2[3], nsvA[p][3]));
                        u64 q = mul2_(mul2_(t0,t1), mul2_(t2,t3)) & ABSM;
                        if (p==0) st0.x = q; else st0.y = q;
                        u64 v0 = fma2_(cu2[0], cvB[p][0], mul2_(su2[0], nsvB[p][0]));
                        u64 v1 = fma2_(cu2[1], cvB[p][1], mul2_(su2[1], nsvB[p][1]));
                        u64 v2 = fma2_(cu2[2], cvB[p][2], mul2_(su2[2], nsvB[p][2]));
                        u64 v3 = fma2_(cu2[3], cvB[p][3], mul2_(su2[3], nsvB[p][3]));
                        u64 qq = mul2_(mul2_(v0,v1), mul2_(v2,v3)) & ABSM;
                        if (p==0) st1.x = qq; else st1.y = qq;
                    }
                    *(ulonglong2*)(qk_out + (size_t)m*NSUP + ncol0)      = st0;
                    *(ulonglong2*)(qk_out + (size_t)m*NSUP + ncol0 + 64) = st1;
                }
            }
        }
    }
}

extern "C" void kernel_launch(void* const* d_in, const int* in_sizes, int n_in,
                              void* d_out, int out_size)
{
    const float* x   = (const float*)d_in[0];
    const float* sv  = (const float*)d_in[1];
    const float* Wf  = (const float*)d_in[2];
    const float* bf  = (const float*)d_in[3];
    const float* Wi  = (const float*)d_in[4];
    const float* bi  = (const float*)d_in[5];
    const float* Wu  = (const float*)d_in[6];
    const float* bu  = (const float*)d_in[7];
    const float* Wo  = (const float*)d_in[8];
    const float* bo  = (const float*)d_in[9];
    const float* pf  = (const float*)d_in[10];
    const float* pi_ = (const float*)d_in[11];
    const float* pu  = (const float*)d_in[12];
    const float* po  = (const float*)d_in[13];
    const float* qkp = (const float*)d_in[14];

    hyb_kernel<<<NBLOCKS, 256>>>(x, sv, Wf, bf, Wi, bi, Wu, bu, Wo, bo,
                                 pf, pi_, pu, po, qkp, (float*)d_out);
}

// round 17
// speedup vs baseline: 1.4375x; 1.0708x over previous
#include <cuda_runtime.h>

#define T_STEPS 128
#define BATCH   64
#define DFEAT   32
#define NSUP    1024
#define MROWS   8192
#define LSTM_BLOCKS 16
#define NBLOCKS (LSTM_BLOCKS + 256)   // 64 M-tiles x 4 blocks, each 2 N-subtiles

#define OUTS_OFF 0
#define RBF_OFF  32768
#define QK_OFF   (32768 + MROWS*NSUP)

#define LOG2E 1.4426950408889634f

typedef unsigned long long u64;

__device__ __forceinline__ float tanh_hw(float z){
    float r;
    asm("tanh.approx.f32 %0, %1;" : "=f"(r) : "f"(z));
    return r;
}
__device__ __forceinline__ float sigm_hw(float z){
    return fmaf(0.5f, tanh_hw(0.5f*z), 0.5f);
}
__device__ __forceinline__ float ex2_hw(float z){
    float r;
    asm("ex2.approx.f32 %0, %1;" : "=f"(r) : "f"(z));
    return r;
}

// ---- packed fp32x2 helpers ----
__device__ __forceinline__ u64 pack2(float lo, float hi){
    u64 r;
    asm("mov.b64 %0, {%1,%2};" : "=l"(r) : "f"(lo), "f"(hi));
    return r;
}
__device__ __forceinline__ void unpack2(u64 v, float& lo, float& hi){
    asm("mov.b64 {%0,%1}, %2;" : "=f"(lo), "=f"(hi) : "l"(v));
}
__device__ __forceinline__ u64 fma2_(u64 a, u64 b, u64 c){
    u64 d;
    asm("fma.rn.f32x2 %0, %1, %2, %3;" : "=l"(d) : "l"(a), "l"(b), "l"(c));
    return d;
}
__device__ __forceinline__ u64 mul2_(u64 a, u64 b){
    u64 d;
    asm("mul.rn.f32x2 %0, %1, %2;" : "=l"(d) : "l"(a), "l"(b));
    return d;
}
__device__ __forceinline__ u64 add2_(u64 a, u64 b){
    u64 d;
    asm("add.rn.f32x2 %0, %1, %2;" : "=l"(d) : "l"(a), "l"(b));
    return d;
}
// streaming (evict-first) 16B stores for write-once output
__device__ __forceinline__ void st_cs_f4(float* p, float4 v){
    asm volatile("st.global.cs.v4.f32 [%0], {%1,%2,%3,%4};"
                 :: "l"(p), "f"(v.x), "f"(v.y), "f"(v.z), "f"(v.w) : "memory");
}
__device__ __forceinline__ void st_cs_u2(float* p, ulonglong2 v){
    asm volatile("st.global.cs.v2.u64 [%0], {%1,%2};"
                 :: "l"(p), "l"(v.x), "l"(v.y) : "memory");
}

__global__ __launch_bounds__(256, 2)
void hyb_kernel(const float* __restrict__ x,
                const float* __restrict__ sv,
                const float* __restrict__ Wf, const float* __restrict__ bf,
                const float* __restrict__ Wi, const float* __restrict__ bi,
                const float* __restrict__ Wu, const float* __restrict__ bu,
                const float* __restrict__ Wo, const float* __restrict__ bo,
                const float* __restrict__ pf, const float* __restrict__ pi,
                const float* __restrict__ pu, const float* __restrict__ po,
                const float* __restrict__ qkp,
                float* __restrict__ out)
{
    if (blockIdx.x < LSTM_BLOCKS) {
        // ================= LSTM role: one warp per batch element =================
        int warp = threadIdx.x >> 5;
        if (warp >= 4) return;
        int lane = threadIdx.x & 31;
        int b    = blockIdx.x * 4 + warp;
        int sl   = lane & 15;
        int g    = sl >> 2;
        int w    = sl & 3;

        const float* W  = (g==0)?Wf:(g==1)?Wi:(g==2)?Wu:Wo;
        const float* bb = (g==0)?bf:(g==1)?bi:(g==2)?bu:bo;
        const float* pp = (g==0)?pf:(g==1)?pi:(g==2)?pu:po;

        float wx[32];
        #pragma unroll
        for (int d=0; d<32; d++) wx[d] = W[w*36 + d];
        float wh0 = W[w*36+32], wh1 = W[w*36+33], wh2 = W[w*36+34], wh3 = W[w*36+35];
        float bias = bb[w] + pp[w];

        float h0=0.f,h1=0.f,h2=0.f,h3=0.f,cst=0.f;
        const unsigned FULL = 0xffffffffu;

        float dcur;
        {
            const float4* xp = (const float4*)(x + (size_t)b*DFEAT);
            float s0=bias, s1=0.f, s2=0.f, s3=0.f;
            #pragma unroll
            for (int q=0;q<8;q++){
                float4 v = xp[q];
                s0 = fmaf(wx[4*q+0], v.x, s0);
                s1 = fmaf(wx[4*q+1], v.y, s1);
                s2 = fmaf(wx[4*q+2], v.z, s2);
                s3 = fmaf(wx[4*q+3], v.w, s3);
            }
            dcur = (s0+s1)+(s2+s3);
        }

        for (int t=0; t<T_STEPS; t++){
            float theta = dcur;
            theta = fmaf(wh0,h0,theta);
            theta = fmaf(wh1,h1,theta);
            theta = fmaf(wh2,h2,theta);
            theta = fmaf(wh3,h3,theta);
            float cth = __cosf(theta);

            float dnext = bias;
            if (t < T_STEPS-1){
                const float4* xp = (const float4*)(x + ((size_t)(t+1)*BATCH + b)*DFEAT);
                float s0=bias, s1=0.f, s2=0.f, s3=0.f;
                #pragma unroll
                for (int q=0;q<8;q++){
                    float4 v = __ldg(&xp[q]);
                    s0 = fmaf(wx[4*q+0], v.x, s0);
                    s1 = fmaf(wx[4*q+1], v.y, s1);
                    s2 = fmaf(wx[4*q+2], v.z, s2);
                    s3 = fmaf(wx[4*q+3], v.w, s3);
                }
                dnext = (s0+s1)+(s2+s3);
            }

            int base = lane & ~3;
            float c0 = __shfl_sync(FULL, cth, base+0);
            float c1 = __shfl_sync(FULL, cth, base+1);
            float c2 = __shfl_sync(FULL, cth, base+2);
            float c3 = __shfl_sync(FULL, cth, base+3);
            float p01  = c0*c1;
            float p012 = p01*c2;
            float z = (w==0) ? c1*c2*c3 : (w==1) ? p01 : (w==2) ? p012 : p012*c3;
            float val = (g==2) ? tanh_hw(z) : sigm_hw(z);

            int hb = lane & 16;
            float fv = __shfl_sync(FULL, val, hb + 0  + w);
            float iv = __shfl_sync(FULL, val, hb + 4  + w);
            float uv = __shfl_sync(FULL, val, hb + 8  + w);
            float ov = __shfl_sync(FULL, val, hb + 12 + w);

            cst = fmaf(fv, cst, iv*uv);
            float ht = ov * tanh_hw(cst);
            if (lane < 4) out[OUTS_OFF + t*(BATCH*4) + b*4 + w] = ht;

            h0 = __shfl_sync(FULL, ht, base+0);
            h1 = __shfl_sync(FULL, ht, base+1);
            h2 = __shfl_sync(FULL, ht, base+2);
            h3 = __shfl_sync(FULL, ht, base+3);
            dcur = dnext;
        }
        return;
    }

    // ===== rbf + qk role: 2 N-adjacent 128x128 tiles, single prologue, 1 barrier =====
    __shared__ __align__(16) float xs[32][132];      // k-major x tile
    __shared__ __align__(16) float ss[2][32][132];   // k-major s tiles (both subtiles)
    __shared__ float xrow[128][9];                   // cos u[4], sin u[4], ||x||^2 * log2e
    __shared__ float srow[2][128][9];                // cos v[4], -sin v[4], ||s||^2 * log2e

    int bid2 = blockIdx.x - LSTM_BLOCKS;
    int mt = bid2 >> 2;
    int np = bid2 & 3;
    int m0 = mt * 128;
    int n0base = np * 256;
    int tid = threadIdx.x;
    int rbase = tid >> 3;
    int kc    = (tid & 7) * 4;

    // ---- single prologue: all gmem traffic up front ----
    {
        #pragma unroll
        for (int pass=0; pass<4; pass++){
            int r = rbase + pass*32;
            float4 v  = *(const float4*)(x  + (size_t)(m0 + r)*DFEAT + kc);
            float4 u0 = *(const float4*)(sv + (size_t)(n0base + r)*DFEAT + kc);
            float4 u1 = *(const float4*)(sv + (size_t)(n0base + 128 + r)*DFEAT + kc);
            xs[kc+0][r]=v.x;  xs[kc+1][r]=v.y;  xs[kc+2][r]=v.z;  xs[kc+3][r]=v.w;
            ss[0][kc+0][r]=u0.x; ss[0][kc+1][r]=u0.y; ss[0][kc+2][r]=u0.z; ss[0][kc+3][r]=u0.w;
            ss[1][kc+0][r]=u1.x; ss[1][kc+1][r]=u1.y; ss[1][kc+2][r]=u1.z; ss[1][kc+3][r]=u1.w;
        }
    }
    if (tid < 128){   // xrow factors
        const float4* xp = (const float4*)(x + (size_t)(m0 + tid)*DFEAT);
        float4 v0 = xp[0];
        float nrm = 0.f;
        #pragma unroll
        for (int q=0;q<8;q++){
            float4 v = xp[q];
            nrm = fmaf(v.x,v.x,nrm); nrm = fmaf(v.y,v.y,nrm);
            nrm = fmaf(v.z,v.z,nrm); nrm = fmaf(v.w,v.w,nrm);
        }
        float fw[4] = {v0.x, v0.y, v0.z, v0.w};
        #pragma unroll
        for (int w=0; w<4; w++){
            float th = fmaf(fw[w], 0.5f, qkp[w]*0.5f);
            float s_, c_;
            __sincosf(th, &s_, &c_);
            xrow[tid][w]   = c_;
            xrow[tid][4+w] = s_;
        }
        xrow[tid][8] = nrm * LOG2E;
    } else {          // srow factors for BOTH subtiles
        int r = tid - 128;
        #pragma unroll
        for (int sub=0; sub<2; sub++){
            const float4* sp = (const float4*)(sv + (size_t)(n0base + sub*128 + r)*DFEAT);
            float4 v0 = sp[0];
            float nrm = 0.f;
            #pragma unroll
            for (int q=0;q<8;q++){
                float4 v = sp[q];
                nrm = fmaf(v.x,v.x,nrm); nrm = fmaf(v.y,v.y,nrm);
                nrm = fmaf(v.z,v.z,nrm); nrm = fmaf(v.w,v.w,nrm);
            }
            float fw[4] = {v0.x, v0.y, v0.z, v0.w};
            #pragma unroll
            for (int w=0; w<4; w++){
                float th = fmaf(fw[w], 0.5f, qkp[w]*0.5f);
                float s_, c_;
                __sincosf(th, &s_, &c_);
                srow[sub][r][w]   = c_;
                srow[sub][r][4+w] = -s_;     // store sin negated
            }
            srow[sub][r][8] = nrm * LOG2E;
        }
    }
    __syncthreads();   // the only barrier

    int tx = tid & 15;
    int ty = tid >> 4;
    float* rbf_out = out + RBF_OFF;
    float* qk_out  = out + QK_OFF;
    const u64 TWOL = pack2(2.0f*LOG2E, 2.0f*LOG2E);

    #pragma unroll 1
    for (int sub = 0; sub < 2; sub++){
        int n0 = n0base + sub*128;
        const float (*ssb)[132] = ss[sub];
        const float (*srb)[9]   = srow[sub];

        // ---- main GEMM loop: 8 rows x 8 cols per thread, packed f32x2 along N ----
        u64 acc2[2][4][2][2];
        #pragma unroll
        for (int ii=0;ii<2;ii++)
            #pragma unroll
            for (int r=0;r<4;r++)
                #pragma unroll
                for (int jj=0;jj<2;jj++){ acc2[ii][r][jj][0]=0ull; acc2[ii][r][jj][1]=0ull; }

        #pragma unroll 8
        for (int k=0; k<32; k++){
            float4 a0 = ((const float4*)xs[k])[ty];
            float4 a1 = ((const float4*)xs[k])[ty+16];
            ulonglong2 B0 = ((const ulonglong2*)ssb[k])[tx];
            ulonglong2 B1 = ((const ulonglong2*)ssb[k])[tx+16];
            u64 aa;
            aa = pack2(a0.x,a0.x);
            acc2[0][0][0][0]=fma2_(aa,B0.x,acc2[0][0][0][0]); acc2[0][0][0][1]=fma2_(aa,B0.y,acc2[0][0][0][1]);
            acc2[0][0][1][0]=fma2_(aa,B1.x,acc2[0][0][1][0]); acc2[0][0][1][1]=fma2_(aa,B1.y,acc2[0][0][1][1]);
            aa = pack2(a0.y,a0.y);
            acc2[0][1][0][0]=fma2_(aa,B0.x,acc2[0][1][0][0]); acc2[0][1][0][1]=fma2_(aa,B0.y,acc2[0][1][0][1]);
            acc2[0][1][1][0]=fma2_(aa,B1.x,acc2[0][1][1][0]); acc2[0][1][1][1]=fma2_(aa,B1.y,acc2[0][1][1][1]);
            aa = pack2(a0.z,a0.z);
            acc2[0][2][0][0]=fma2_(aa,B0.x,acc2[0][2][0][0]); acc2[0][2][0][1]=fma2_(aa,B0.y,acc2[0][2][0][1]);
            acc2[0][2][1][0]=fma2_(aa,B1.x,acc2[0][2][1][0]); acc2[0][2][1][1]=fma2_(aa,B1.y,acc2[0][2][1][1]);
            aa = pack2(a0.w,a0.w);
            acc2[0][3][0][0]=fma2_(aa,B0.x,acc2[0][3][0][0]); acc2[0][3][0][1]=fma2_(aa,B0.y,acc2[0][3][0][1]);
            acc2[0][3][1][0]=fma2_(aa,B1.x,acc2[0][3][1][0]); acc2[0][3][1][1]=fma2_(aa,B1.y,acc2[0][3][1][1]);
            aa = pack2(a1.x,a1.x);
            acc2[1][0][0][0]=fma2_(aa,B0.x,acc2[1][0][0][0]); acc2[1][0][0][1]=fma2_(aa,B0.y,acc2[1][0][0][1]);
            acc2[1][0][1][0]=fma2_(aa,B1.x,acc2[1][0][1][0]); acc2[1][0][1][1]=fma2_(aa,B1.y,acc2[1][0][1][1]);
            aa = pack2(a1.y,a1.y);
            acc2[1][1][0][0]=fma2_(aa,B0.x,acc2[1][1][0][0]); acc2[1][1][0][1]=fma2_(aa,B0.y,acc2[1][1][0][1]);
            acc2[1][1][1][0]=fma2_(aa,B1.x,acc2[1][1][1][0]); acc2[1][1][1][1]=fma2_(aa,B1.y,acc2[1][1][1][1]);
            aa = pack2(a1.z,a1.z);
            acc2[1][2][0][0]=fma2_(aa,B0.x,acc2[1][2][0][0]); acc2[1][2][0][1]=fma2_(aa,B0.y,acc2[1][2][0][1]);
            acc2[1][2][1][0]=fma2_(aa,B1.x,acc2[1][2][1][0]); acc2[1][2][1][1]=fma2_(aa,B1.y,acc2[1][2][1][1]);
            aa = pack2(a1.w,a1.w);
            acc2[1][3][0][0]=fma2_(aa,B0.x,acc2[1][3][0][0]); acc2[1][3][0][1]=fma2_(aa,B0.y,acc2[1][3][0][1]);
            acc2[1][3][1][0]=fma2_(aa,B1.x,acc2[1][3][1][0]); acc2[1][3][1][1]=fma2_(aa,B1.y,acc2[1][3][1][1]);
        }

        const int ncol0 = n0 + tx*4;

        // ---- rbf epilogue: 2^(2L*dot - L*xn - L*sn) via MUFU ex2, streaming stores ----
        {
            u64 nsnA0 = pack2(-srb[tx*4+0][8], -srb[tx*4+1][8]);
            u64 nsnA1 = pack2(-srb[tx*4+2][8], -srb[tx*4+3][8]);
            u64 nsnB0 = pack2(-srb[tx*4+64][8], -srb[tx*4+65][8]);
            u64 nsnB1 = pack2(-srb[tx*4+66][8], -srb[tx*4+67][8]);
            #pragma unroll
            for (int ii=0; ii<2; ii++){
                #pragma unroll
                for (int r=0; r<4; r++){
                    int mi = ty*4 + r + 64*ii;
                    float xn = xrow[mi][8];
                    u64 nxn2 = pack2(-xn, -xn);
                    int m = m0 + mi;
                    u64 g0 = fma2_(acc2[ii][r][0][0], TWOL, add2_(nxn2, nsnA0));
                    u64 g1 = fma2_(acc2[ii][r][0][1], TWOL, add2_(nxn2, nsnA1));
                    u64 g2 = fma2_(acc2[ii][r][1][0], TWOL, add2_(nxn2, nsnB0));
                    u64 g3 = fma2_(acc2[ii][r][1][1], TWOL, add2_(nxn2, nsnB1));
                    float4 o0, o1;
                    unpack2(g0, o0.x, o0.y);  unpack2(g1, o0.z, o0.w);
                    unpack2(g2, o1.x, o1.y);  unpack2(g3, o1.z, o1.w);
                    o0.x = ex2_hw(o0.x); o0.y = ex2_hw(o0.y);
                    o0.z = ex2_hw(o0.z); o0.w = ex2_hw(o0.w);
                    o1.x = ex2_hw(o1.x); o1.y = ex2_hw(o1.y);
                    o1.z = ex2_hw(o1.z); o1.w = ex2_hw(o1.w);
                    st_cs_f4(rbf_out + (size_t)m*NSUP + ncol0,      o0);
                    st_cs_f4(rbf_out + (size_t)m*NSUP + ncol0 + 64, o1);
                }
            }
        }

        // ---- qk epilogue: |prod_w (cu*cv - su*sv)|, streaming stores ----
        {
            u64 cvA[2][4], nsvA[2][4], cvB[2][4], nsvB[2][4];
            #pragma unroll
            for (int p=0; p<2; p++){
                int c0 = tx*4 + 2*p, c1 = c0 + 1;
                #pragma unroll
                for (int w=0; w<4; w++){
                    cvA[p][w]  = pack2(srb[c0][w],    srb[c1][w]);
                    nsvA[p][w] = pack2(srb[c0][4+w],  srb[c1][4+w]);    // already negated
                    cvB[p][w]  = pack2(srb[c0+64][w], srb[c1+64][w]);
                    nsvB[p][w] = pack2(srb[c0+64][4+w], srb[c1+64][4+w]);
                }
            }
            const u64 ABSM = 0x7FFFFFFF7FFFFFFFull;
            #pragma unroll
            for (int ii=0; ii<2; ii++){
                #pragma unroll
                for (int r=0; r<4; r++){
                    int mi = ty*4 + r + 64*ii;
                    int m = m0 + mi;
                    u64 cu2[4], su2[4];
                    #pragma unroll
                    for (int w=0; w<4; w++){
                        float cu = xrow[mi][w], su = xrow[mi][4+w];
                        cu2[w] = pack2(cu,cu); su2[w] = pack2(su,su);
                    }
                    ulonglong2 st0, st1;
                    #pragma unroll
                    for (int p=0; p<2; p++){
                        u64 t0 = fma2_(cu2[0], cvA[p][0], mul2_(su2[0], nsvA[p][0]));
                        u64 t1 = fma2_(cu2[1], cvA[p][1], mul2_(su2[1], nsvA[p][1]));
                        u64 t2 = fma2_(cu2[2], cvA[p][2], mul2_(su2[2], nsvA[p][2]));
                        u64 t3 = fma2_(cu2[3], cvA[p][3], mul2_(su2[3], nsvA[p][3]));
                        u64 q = mul2_(mul2_(t0,t1), mul2_(t2,t3)) & ABSM;
                        if (p==0) st0.x = q; else st0.y = q;
                        u64 v0 = fma2_(cu2[0], cvB[p][0], mul2_(su2[0], nsvB[p][0]));
                        u64 v1 = fma2_(cu2[1], cvB[p][1], mul2_(su2[1], nsvB[p][1]));
                        u64 v2 = fma2_(cu2[2], cvB[p][2], mul2_(su2[2], nsvB[p][2]));
                        u64 v3 = fma2_(cu2[3], cvB[p][3], mul2_(su2[3], nsvB[p][3]));
                        u64 qq = mul2_(mul2_(v0,v1), mul2_(v2,v3)) & ABSM;
                        if (p==0) st1.x = qq; else st1.y = qq;
                    }
                    st_cs_u2(qk_out + (size_t)m*NSUP + ncol0,      st0);
                    st_cs_u2(qk_out + (size_t)m*NSUP + ncol0 + 64, st1);
                }
            }
        }
    }
}

extern "C" void kernel_launch(void* const* d_in, const int* in_sizes, int n_in,
                              void* d_out, int out_size)
{
    const float* x   = (const float*)d_in[0];
    const float* sv  = (const float*)d_in[1];
    const float* Wf  = (const float*)d_in[2];
    const float* bf  = (const float*)d_in[3];
    const float* Wi  = (const float*)d_in[4];
    const float* bi  = (const float*)d_in[5];
    const float* Wu  = (const float*)d_in[6];
    const float* bu  = (const float*)d_in[7];
    const float* Wo  = (const float*)d_in[8];
    const float* bo  = (const float*)d_in[9];
    const float* pf  = (const float*)d_in[10];
    const float* pi_ = (const float*)d_in[11];
    const float* pu  = (const float*)d_in[12];
    const float* po  = (const float*)d_in[13];
    const float* qkp = (const float*)d_in[14];

    hyb_kernel<<<NBLOCKS, 256>>>(x, sv, Wf, bf, Wi, bi, Wu, bu, Wo, bo,
                                 pf, pi_, pu, po, qkp, (float*)d_out);
}